// round 6
// baseline (speedup 1.0000x reference)
#include <cuda_runtime.h>
#include <cuda_bf16.h>
#include <cstdint>

#define NN    20000
#define NPAD  20096   // 157 * 128
#define NE    320000

// ---------------- scratch (static device memory, no allocs) ----------------
__device__ float  g_H[(size_t)NPAD * 1024];
__device__ float  g_A[(size_t)NPAD * 1024];
__device__ float  g_B[(size_t)NPAD * 1024];
__device__ float2 g_rel[NE];
__device__ float  g_cnt[NPAD];
__device__ float  g_inv[NPAD];
__device__ float  g_msk[NPAD];

__device__ __forceinline__ float* selbuf(int s) {
    return s == 0 ? g_H : (s == 1 ? g_A : g_B);
}

// ---------------- small utility kernels ----------------
__global__ void k_zero_B(long n4) {
    long i = (long)blockIdx.x * blockDim.x + threadIdx.x;
    long stride = (long)gridDim.x * blockDim.x;
    float4 z = make_float4(0.f, 0.f, 0.f, 0.f);
    float4* p = (float4*)g_B;
    for (; i < n4; i += stride) p[i] = z;
}

__global__ void k_zero_cnt() {
    int i = blockIdx.x * blockDim.x + threadIdx.x;
    if (i < NPAD) g_cnt[i] = 0.f;
}

__global__ void k_copy_h(const float* __restrict__ src) {
    int i = blockIdx.x * blockDim.x + threadIdx.x;
    if (i < NPAD * 16 / 4) {
        float4 v = (i < NN * 16 / 4) ? ((const float4*)src)[i] : make_float4(0.f, 0.f, 0.f, 0.f);
        ((float4*)g_H)[i] = v;
    }
}

__global__ void k_prep(const int* __restrict__ ei, const float* __restrict__ pos) {
    int e = blockIdx.x * blockDim.x + threadIdx.x;
    if (e < NE) {
        int s = ei[e];
        int d = ei[NE + e];
        float2 ps = ((const float2*)pos)[s];
        float2 pd = ((const float2*)pos)[d];
        g_rel[e] = make_float2(ps.x - pd.x, ps.y - pd.y);
        atomicAdd(g_cnt + d, 1.0f);
    }
}

__global__ void k_fin() {
    int i = blockIdx.x * blockDim.x + threadIdx.x;
    if (i < NPAD) {
        float c = g_cnt[i];
        g_inv[i] = 1.0f / fmaxf(c, 1.0f);
        g_msk[i] = (c > 0.0f) ? 1.0f : 0.0f;
    }
}

// ---------------- mma helpers ----------------
__device__ __forceinline__ void ldsm4(uint32_t& r0, uint32_t& r1, uint32_t& r2, uint32_t& r3,
                                      const void* p) {
    uint32_t addr = (uint32_t)__cvta_generic_to_shared(p);
    asm volatile("ldmatrix.sync.aligned.m8n8.x4.shared.b16 {%0,%1,%2,%3}, [%4];\n"
                 : "=r"(r0), "=r"(r1), "=r"(r2), "=r"(r3) : "r"(addr));
}

__device__ __forceinline__ void mma_bf16(float* c, const uint32_t* a, uint32_t b0, uint32_t b1) {
    asm volatile(
        "mma.sync.aligned.m16n8k16.row.col.f32.bf16.bf16.f32 "
        "{%0,%1,%2,%3}, {%4,%5,%6,%7}, {%8,%9}, {%0,%1,%2,%3};\n"
        : "+f"(c[0]), "+f"(c[1]), "+f"(c[2]), "+f"(c[3])
        : "r"(a[0]), "r"(a[1]), "r"(a[2]), "r"(a[3]), "r"(b0), "r"(b1));
}

__device__ __forceinline__ void split1(float a, __nv_bfloat16& h, __nv_bfloat16& l) {
    h = __float2bfloat16(a);
    l = __float2bfloat16(a - __bfloat162float(h));
}

// ---------------- tensor-core GEMM (3xBF16 split) ----------------
// C[M=NPAD, N] = A[M,K] @ W[K,N] (+epilogue). K%32==0, N%128==0.
template <bool RELU, bool SCALED>
__global__ __launch_bounds__(512) void tgemm_kernel(
    int K, int N, int srcSel, int dstSel,
    const float* __restrict__ W, const float* __restrict__ bias)
{
    constexpr int BM = 128, BN = 128, BK = 32, BKP = 40;  // BKP*2=80B rows, 16B-aligned
    __shared__ __align__(16) __nv_bfloat16 As_hi[BM][BKP];
    __shared__ __align__(16) __nv_bfloat16 As_lo[BM][BKP];
    __shared__ __align__(16) __nv_bfloat16 Bs_hi[BN][BKP];  // transposed: [n][k]
    __shared__ __align__(16) __nv_bfloat16 Bs_lo[BN][BKP];

    const float* A = selbuf(srcSel);
    float*       C = selbuf(dstSel);

    const int bm = blockIdx.y * BM;
    const int bn = blockIdx.x * BN;
    const int tid  = threadIdx.x;
    const int warp = tid >> 5;
    const int lane = tid & 31;
    const int warp_m = warp >> 2;   // 0..3 -> 32-row strip
    const int warp_n = warp & 3;    // 0..3 -> 32-col strip

    float acc[2][4][4];   // [mt][nt][reg]
#pragma unroll
    for (int i = 0; i < 2; i++)
#pragma unroll
        for (int j = 0; j < 4; j++)
#pragma unroll
            for (int r = 0; r < 4; r++) acc[i][j][r] = 0.f;

    const int a_row = lane & 15;
    const int a_koff = (lane >> 4) << 3;                // 0 or 8
    const int b_row = (lane & 7) + ((lane & 16) >> 1);  // 0..15
    const int b_koff = lane & 8;                        // 0 or 8

    for (int k0 = 0; k0 < K; k0 += BK) {
        // A tile: 128x32 floats = 1024 float4, 2 per thread
#pragma unroll
        for (int i = 0; i < 2; i++) {
            int idx = tid + i * 512;
            int r = idx >> 3;
            int c4 = (idx & 7) << 2;
            float4 v = *(const float4*)(A + (long)(bm + r) * K + k0 + c4);
            __nv_bfloat16 h0, h1, h2, h3, l0, l1, l2, l3;
            split1(v.x, h0, l0); split1(v.y, h1, l1);
            split1(v.z, h2, l2); split1(v.w, h3, l3);
            __nv_bfloat162 ph0 = {h0, h1}, ph1 = {h2, h3};
            __nv_bfloat162 pl0 = {l0, l1}, pl1 = {l2, l3};
            *(__nv_bfloat162*)&As_hi[r][c4]     = ph0;
            *(__nv_bfloat162*)&As_hi[r][c4 + 2] = ph1;
            *(__nv_bfloat162*)&As_lo[r][c4]     = pl0;
            *(__nv_bfloat162*)&As_lo[r][c4 + 2] = pl1;
        }
        // W tile 32x128, transposed into Bs[n][k]
#pragma unroll
        for (int i = 0; i < 2; i++) {
            int idx = tid + i * 512;
            int kk = idx >> 5;
            int nf = (idx & 31) << 2;
            float4 v = *(const float4*)(W + (long)(k0 + kk) * N + bn + nf);
            __nv_bfloat16 h, l;
            split1(v.x, h, l); Bs_hi[nf + 0][kk] = h; Bs_lo[nf + 0][kk] = l;
            split1(v.y, h, l); Bs_hi[nf + 1][kk] = h; Bs_lo[nf + 1][kk] = l;
            split1(v.z, h, l); Bs_hi[nf + 2][kk] = h; Bs_lo[nf + 2][kk] = l;
            split1(v.w, h, l); Bs_hi[nf + 3][kk] = h; Bs_lo[nf + 3][kk] = l;
        }
        __syncthreads();

#pragma unroll
        for (int ks = 0; ks < BK; ks += 16) {
            uint32_t ah[2][4], al[2][4];
#pragma unroll
            for (int mt = 0; mt < 2; mt++) {
                int m0 = warp_m * 32 + mt * 16;
                ldsm4(ah[mt][0], ah[mt][1], ah[mt][2], ah[mt][3],
                      &As_hi[m0 + a_row][ks + a_koff]);
                ldsm4(al[mt][0], al[mt][1], al[mt][2], al[mt][3],
                      &As_lo[m0 + a_row][ks + a_koff]);
            }
#pragma unroll
            for (int pair = 0; pair < 2; pair++) {
                int n0 = warp_n * 32 + pair * 16;
                uint32_t bh0, bh1, bh2, bh3, bl0, bl1, bl2, bl3;
                ldsm4(bh0, bh1, bh2, bh3, &Bs_hi[n0 + b_row][ks + b_koff]);
                ldsm4(bl0, bl1, bl2, bl3, &Bs_lo[n0 + b_row][ks + b_koff]);
#pragma unroll
                for (int mt = 0; mt < 2; mt++) {
                    float* c0 = acc[mt][pair * 2 + 0];
                    float* c1 = acc[mt][pair * 2 + 1];
                    mma_bf16(c0, ah[mt], bh0, bh1);
                    mma_bf16(c0, ah[mt], bl0, bl1);
                    mma_bf16(c0, al[mt], bh0, bh1);
                    mma_bf16(c1, ah[mt], bh2, bh3);
                    mma_bf16(c1, ah[mt], bl2, bl3);
                    mma_bf16(c1, al[mt], bh2, bh3);
                }
            }
        }
        __syncthreads();
    }

    // epilogue
    const int rbase = bm + warp_m * 32 + (lane >> 2);
    const int cbase = bn + warp_n * 32 + 2 * (lane & 3);
#pragma unroll
    for (int mt = 0; mt < 2; mt++) {
#pragma unroll
        for (int half = 0; half < 2; half++) {
            int r = rbase + mt * 16 + half * 8;
            float scale = SCALED ? g_inv[r] : 1.0f;
            float bmsk  = SCALED ? g_msk[r] : 1.0f;
            float* crow = C + (long)r * N;
#pragma unroll
            for (int nt = 0; nt < 4; nt++) {
                int c = cbase + nt * 8;
                float2 bv = *(const float2*)(bias + c);
                float v0 = acc[mt][nt][half * 2 + 0] * scale + bv.x * bmsk;
                float v1 = acc[mt][nt][half * 2 + 1] * scale + bv.y * bmsk;
                if (RELU) { v0 = fmaxf(v0, 0.f); v1 = fmaxf(v1, 0.f); }
                *(float2*)(crow + c) = make_float2(v0, v1);
            }
        }
    }
}

// ---------------- SIMT SGEMM for K=16 first layer ----------------
__global__ __launch_bounds__(256) void sgemm16_kernel(
    int N, const float* __restrict__ B, const float* __restrict__ bias)
{
    constexpr int BM = 128, BN = 128, BK = 16, TM = 8, TN = 8;
    __shared__ __align__(16) float As[BK][BM];
    __shared__ __align__(16) float Bs[BK][BN];
    const float* A = g_H;
    float*       C = g_A;
    const int bm = blockIdx.y * BM;
    const int bn = blockIdx.x * BN;
    const int tid = threadIdx.x;
    const int arow = tid >> 2, acol = (tid & 3) << 2;
    const int brow = tid >> 5, bcol = (tid & 31) << 2;
    const int ty = (tid >> 4) * TM, tx = (tid & 15) * TN;
    float acc[TM][TN];
#pragma unroll
    for (int i = 0; i < TM; i++)
#pragma unroll
        for (int j = 0; j < TN; j++) acc[i][j] = 0.f;
    const int K = 16;
    {
#pragma unroll
        for (int i = 0; i < 2; i++) {
            int r = arow + i * 64;
            float4 v = *(const float4*)(A + (long)(bm + r) * K + acol);
            As[acol + 0][r] = v.x; As[acol + 1][r] = v.y;
            As[acol + 2][r] = v.z; As[acol + 3][r] = v.w;
        }
#pragma unroll
        for (int i = 0; i < 2; i++) {
            int r = brow + i * 8;
            *(float4*)(&Bs[r][bcol]) = *(const float4*)(B + (long)r * N + bn + bcol);
        }
        __syncthreads();
#pragma unroll
        for (int kk = 0; kk < BK; kk++) {
            float ra[TM], rb[TN];
            *(float4*)(ra)     = *(const float4*)(&As[kk][ty]);
            *(float4*)(ra + 4) = *(const float4*)(&As[kk][ty + 4]);
            *(float4*)(rb)     = *(const float4*)(&Bs[kk][tx]);
            *(float4*)(rb + 4) = *(const float4*)(&Bs[kk][tx + 4]);
#pragma unroll
            for (int i = 0; i < TM; i++)
#pragma unroll
                for (int j = 0; j < TN; j++) acc[i][j] += ra[i] * rb[j];
        }
    }
#pragma unroll
    for (int i = 0; i < TM; i++) {
        long m = bm + ty + i;
        float* crow = C + m * N + bn + tx;
#pragma unroll
        for (int j = 0; j < TN; j += 4) {
            float4 bv = *(const float4*)(bias + bn + tx + j);
            float4 o;
            o.x = acc[i][j + 0] + bv.x; o.y = acc[i][j + 1] + bv.y;
            o.z = acc[i][j + 2] + bv.z; o.w = acc[i][j + 3] + bv.w;
            *(float4*)(crow + j) = o;
        }
    }
}

// ---------------- per-edge gather + relu + scatter-add ----------------
template <int H, int TPE, int ITERS>
__global__ __launch_bounds__(256) void edge_kernel(
    const int* __restrict__ ei,
    const float* __restrict__ w1p)
{
    static_assert(H == TPE * 4, "one float4 per thread");
    __shared__ __align__(16) float sw0[H];
    __shared__ __align__(16) float sw1[H];
    for (int i = threadIdx.x; i < H; i += 256) {
        sw0[i] = w1p[i];
        sw1[i] = w1p[H + i];
    }
    __syncthreads();

    constexpr int EPB = 256 / TPE;
    const int lane = threadIdx.x & (TPE - 1);
    const int sub  = threadIdx.x / TPE;
    const int v    = lane * 4;

    const float4 w0 = *(const float4*)(sw0 + v);
    const float4 w1 = *(const float4*)(sw1 + v);

    long base = (long)blockIdx.x * EPB * ITERS;
#pragma unroll 1
    for (int it = 0; it < ITERS; it++) {
        long e = base + (long)it * EPB + sub;
        if (e >= NE) return;
        int src = ei[e];
        int dst = ei[NE + e];
        float2 rp = g_rel[e];
        float4 a = *(const float4*)(g_A + (long)src * H + v);
        float4 z;
        z.x = fmaxf(fmaf(rp.x, w0.x, fmaf(rp.y, w1.x, a.x)), 0.f);
        z.y = fmaxf(fmaf(rp.x, w0.y, fmaf(rp.y, w1.y, a.y)), 0.f);
        z.z = fmaxf(fmaf(rp.x, w0.z, fmaf(rp.y, w1.z, a.z)), 0.f);
        z.w = fmaxf(fmaf(rp.x, w0.w, fmaf(rp.y, w1.w, a.w)), 0.f);
        float* out = g_B + (long)dst * H + v;
        atomicAdd(out + 0, z.x);
        atomicAdd(out + 1, z.y);
        atomicAdd(out + 2, z.z);
        atomicAdd(out + 3, z.w);
    }
}

// ---------------- head final: out[M,4] = g_B[M,512] @ W[512,4] + b ----------------
__global__ void k_head_final(const float* __restrict__ W,
                             const float* __restrict__ b, float* __restrict__ out) {
    int warp = (blockIdx.x * blockDim.x + threadIdx.x) >> 5;
    int lane = threadIdx.x & 31;
    if (warp >= NN) return;
    const float* x = g_B + (long)warp * 512;
    float a0 = 0.f, a1 = 0.f, a2 = 0.f, a3 = 0.f;
    for (int k = lane; k < 512; k += 32) {
        float xv = x[k];
        float4 w = *(const float4*)(W + k * 4);
        a0 = fmaf(xv, w.x, a0);
        a1 = fmaf(xv, w.y, a1);
        a2 = fmaf(xv, w.z, a2);
        a3 = fmaf(xv, w.w, a3);
    }
#pragma unroll
    for (int off = 16; off > 0; off >>= 1) {
        a0 += __shfl_down_sync(0xffffffffu, a0, off);
        a1 += __shfl_down_sync(0xffffffffu, a1, off);
        a2 += __shfl_down_sync(0xffffffffu, a2, off);
        a3 += __shfl_down_sync(0xffffffffu, a3, off);
    }
    if (lane == 0) {
        out[warp * 4 + 0] = a0 + b[0];
        out[warp * 4 + 1] = a1 + b[1];
        out[warp * 4 + 2] = a2 + b[2];
        out[warp * 4 + 3] = a3 + b[3];
    }
}

// ---------------- host orchestration ----------------
static void launch_tgemm(int K, int N, int srcSel, int dstSel,
                         const float* W, const float* bias, bool scaled, bool relu) {
    dim3 grid(N / 128, NPAD / 128);
    if (relu) {
        if (scaled) tgemm_kernel<true, true><<<grid, 512>>>(K, N, srcSel, dstSel, W, bias);
        else        tgemm_kernel<true, false><<<grid, 512>>>(K, N, srcSel, dstSel, W, bias);
    } else {
        if (scaled) tgemm_kernel<false, true><<<grid, 512>>>(K, N, srcSel, dstSel, W, bias);
        else        tgemm_kernel<false, false><<<grid, 512>>>(K, N, srcSel, dstSel, W, bias);
    }
}

extern "C" void kernel_launch(void* const* d_in, const int* in_sizes, int n_in,
                              void* d_out, int out_size) {
    const float* h_in = (const float*)d_in[0];
    const float* pos  = (const float*)d_in[1];
    const int*   ei   = (const int*)d_in[2];   // int32 [2, NE]
    const float* l1_w1 = (const float*)d_in[3];
    const float* l1_b1 = (const float*)d_in[4];
    const float* l1_w2 = (const float*)d_in[5];
    const float* l1_b2 = (const float*)d_in[6];
    const float* l2_w1 = (const float*)d_in[7];
    const float* l2_b1 = (const float*)d_in[8];
    const float* l2_w2 = (const float*)d_in[9];
    const float* l2_b2 = (const float*)d_in[10];
    const float* l3_w1 = (const float*)d_in[11];
    const float* l3_b1 = (const float*)d_in[12];
    const float* l3_w2 = (const float*)d_in[13];
    const float* l3_b2 = (const float*)d_in[14];
    const float* l4_w1 = (const float*)d_in[15];
    const float* l4_b1 = (const float*)d_in[16];
    const float* l4_w2 = (const float*)d_in[17];
    const float* l4_b2 = (const float*)d_in[18];
    const float* hd_w1 = (const float*)d_in[19];
    const float* hd_b1 = (const float*)d_in[20];
    const float* hd_w2 = (const float*)d_in[21];
    const float* hd_b2 = (const float*)d_in[22];
    const float* hd_w3 = (const float*)d_in[23];
    const float* hd_b3 = (const float*)d_in[24];

    // --- prep ---
    k_zero_cnt<<<(NPAD + 255) / 256, 256>>>();
    k_prep<<<(NE + 255) / 256, 256>>>(ei, pos);
    k_fin<<<(NPAD + 255) / 256, 256>>>();
    k_copy_h<<<(NPAD * 16 / 4 + 255) / 256, 256>>>(h_in);

    // --- layer 1: 16 -> 128 -> 128 ---  (buffers: 0=g_H, 1=g_A, 2=g_B)
    sgemm16_kernel<<<dim3(1, NPAD / 128), 256>>>(128, l1_w1, l1_b1);
    k_zero_B<<<2048, 256>>>((long)NPAD * 128 / 4);
    edge_kernel<128, 32, 4><<<(NE + 31) / 32, 256>>>(ei, l1_w1 + 16 * 128);
    launch_tgemm(128, 128, 2, 0, l1_w2, l1_b2, true, true);

    // --- layer 2: 128 -> 256 -> 256 ---
    launch_tgemm(128, 256, 0, 1, l2_w1, l2_b1, false, false);
    k_zero_B<<<2048, 256>>>((long)NPAD * 256 / 4);
    edge_kernel<256, 64, 4><<<(NE + 15) / 16, 256>>>(ei, l2_w1 + 128 * 256);
    launch_tgemm(256, 256, 2, 0, l2_w2, l2_b2, true, true);

    // --- layer 3: 256 -> 1024 -> 1024 ---
    launch_tgemm(256, 1024, 0, 1, l3_w1, l3_b1, false, false);
    k_zero_B<<<4096, 256>>>((long)NPAD * 1024 / 4);
    edge_kernel<1024, 256, 16><<<(NE + 15) / 16, 256>>>(ei, l3_w1 + 256 * 1024);
    launch_tgemm(1024, 1024, 2, 0, l3_w2, l3_b2, true, true);

    // --- layer 4: 1024 -> 1024 -> 1024 ---
    launch_tgemm(1024, 1024, 0, 1, l4_w1, l4_b1, false, false);
    k_zero_B<<<4096, 256>>>((long)NPAD * 1024 / 4);
    edge_kernel<1024, 256, 16><<<(NE + 15) / 16, 256>>>(ei, l4_w1 + 1024 * 1024);
    launch_tgemm(1024, 1024, 2, 0, l4_w2, l4_b2, true, true);

    // --- head: 1024 -> 1024 -> 512 -> 4 ---
    launch_tgemm(1024, 1024, 0, 1, hd_w1, hd_b1, false, true);
    launch_tgemm(1024, 512, 1, 2, hd_w2, hd_b2, false, true);
    k_head_final<<<(NN * 32 + 255) / 256, 256>>>(hd_w3, hd_b3, (float*)d_out);
}

// round 7
// speedup vs baseline: 1.8220x; 1.8220x over previous
#include <cuda_runtime.h>
#include <cuda_bf16.h>
#include <cstdint>

#define NN    20000
#define NPAD  20096   // 157 * 128
#define NE    320000

// ---------------- scratch (static device memory, no allocs) ----------------
__device__ float  g_H[(size_t)NPAD * 16];     // input features (padded)
__device__ float  g_A[(size_t)NPAD * 1024];   // GEMM1 output (fp32, read by edge kernel)
__device__ float  g_B[(size_t)NPAD * 1024];   // edge aggregation (fp32) / hd2 out
__device__ __nv_bfloat16 g_Ph[(size_t)NPAD * 1024];  // split of aggregated B (hi)
__device__ __nv_bfloat16 g_Pl[(size_t)NPAD * 1024];  // split of aggregated B (lo)
__device__ __nv_bfloat16 g_Qh[(size_t)NPAD * 1024];  // epilogue bf16 out (hi)
__device__ __nv_bfloat16 g_Ql[(size_t)NPAD * 1024];  // epilogue bf16 out (lo)
__device__ __nv_bfloat16 g_Wh[5095424];       // transposed weights (hi)
__device__ __nv_bfloat16 g_Wl[5095424];       // transposed weights (lo)
__device__ float2 g_rel[NE];
__device__ float  g_cnt[NPAD];
__device__ float  g_inv[NPAD];
__device__ float  g_msk[NPAD];

// weight offsets in g_Wh/g_Wl (element index)
#define OFF_L1W2 0L
#define OFF_L2W1 16384L
#define OFF_L2W2 49152L
#define OFF_L3W1 114688L
#define OFF_L3W2 376832L
#define OFF_L4W1 1425408L
#define OFF_L4W2 2473984L
#define OFF_HDW1 3522560L
#define OFF_HDW2 4571136L

__device__ __forceinline__ void split1(float a, __nv_bfloat16& h, __nv_bfloat16& l) {
    h = __float2bfloat16(a);
    l = __float2bfloat16(a - __bfloat162float(h));
}

// ---------------- small utility kernels ----------------
__global__ void k_zero_B(long n4) {
    long i = (long)blockIdx.x * blockDim.x + threadIdx.x;
    long stride = (long)gridDim.x * blockDim.x;
    float4 z = make_float4(0.f, 0.f, 0.f, 0.f);
    float4* p = (float4*)g_B;
    for (; i < n4; i += stride) p[i] = z;
}

__global__ void k_zero_cnt() {
    int i = blockIdx.x * blockDim.x + threadIdx.x;
    if (i < NPAD) g_cnt[i] = 0.f;
}

__global__ void k_copy_h(const float* __restrict__ src) {
    int i = blockIdx.x * blockDim.x + threadIdx.x;
    if (i < NPAD * 16 / 4) {
        float4 v = (i < NN * 16 / 4) ? ((const float4*)src)[i] : make_float4(0.f, 0.f, 0.f, 0.f);
        ((float4*)g_H)[i] = v;
    }
}

__global__ void k_prep(const int* __restrict__ ei, const float* __restrict__ pos) {
    int e = blockIdx.x * blockDim.x + threadIdx.x;
    if (e < NE) {
        int s = ei[e];
        int d = ei[NE + e];
        float2 ps = ((const float2*)pos)[s];
        float2 pd = ((const float2*)pos)[d];
        g_rel[e] = make_float2(ps.x - pd.x, ps.y - pd.y);
        atomicAdd(g_cnt + d, 1.0f);
    }
}

__global__ void k_fin() {
    int i = blockIdx.x * blockDim.x + threadIdx.x;
    if (i < NPAD) {
        float c = g_cnt[i];
        g_inv[i] = 1.0f / fmaxf(c, 1.0f);
        g_msk[i] = (c > 0.0f) ? 1.0f : 0.0f;
    }
}

// split g_B[0 .. n4*4) into g_Ph/g_Pl
__global__ void k_splitB(long n4) {
    long i = (long)blockIdx.x * blockDim.x + threadIdx.x;
    long stride = (long)gridDim.x * blockDim.x;
    for (; i < n4; i += stride) {
        float4 v = ((const float4*)g_B)[i];
        __nv_bfloat16 h0, h1, h2, h3, l0, l1, l2, l3;
        split1(v.x, h0, l0); split1(v.y, h1, l1);
        split1(v.z, h2, l2); split1(v.w, h3, l3);
        __nv_bfloat162 ph0; ph0.x = h0; ph0.y = h1;
        __nv_bfloat162 ph1; ph1.x = h2; ph1.y = h3;
        __nv_bfloat162 pl0; pl0.x = l0; pl0.y = l1;
        __nv_bfloat162 pl1; pl1.x = l2; pl1.y = l3;
        *(__nv_bfloat162*)(g_Ph + i * 4)     = ph0;
        *(__nv_bfloat162*)(g_Ph + i * 4 + 2) = ph1;
        *(__nv_bfloat162*)(g_Pl + i * 4)     = pl0;
        *(__nv_bfloat162*)(g_Pl + i * 4 + 2) = pl1;
    }
}

// transpose + split: W[K,N] (row-major, ld=N) -> g_Wh/g_Wl[off + n*K + k]
__global__ void k_tsplit(const float* __restrict__ W, int K, int N, long off) {
    __shared__ float tile[32][33];
    int bx = blockIdx.x, by = blockIdx.y;
    int tx = threadIdx.x, ty = threadIdx.y;  // block (32,8)
#pragma unroll
    for (int j = 0; j < 4; j++) {
        int k = by * 32 + ty + j * 8;
        int n = bx * 32 + tx;
        tile[ty + j * 8][tx] = W[(long)k * N + n];
    }
    __syncthreads();
#pragma unroll
    for (int j = 0; j < 4; j++) {
        int n = bx * 32 + ty + j * 8;
        int k = by * 32 + tx;
        float v = tile[tx][ty + j * 8];
        __nv_bfloat16 h, l;
        split1(v, h, l);
        g_Wh[off + (long)n * K + k] = h;
        g_Wl[off + (long)n * K + k] = l;
    }
}

// ---------------- mma helpers ----------------
__device__ __forceinline__ void ldsm4(uint32_t& r0, uint32_t& r1, uint32_t& r2, uint32_t& r3,
                                      const void* p) {
    uint32_t addr = (uint32_t)__cvta_generic_to_shared(p);
    asm volatile("ldmatrix.sync.aligned.m8n8.x4.shared.b16 {%0,%1,%2,%3}, [%4];\n"
                 : "=r"(r0), "=r"(r1), "=r"(r2), "=r"(r3) : "r"(addr));
}

__device__ __forceinline__ void mma_bf16(float* c, const uint32_t* a, uint32_t b0, uint32_t b1) {
    asm volatile(
        "mma.sync.aligned.m16n8k16.row.col.f32.bf16.bf16.f32 "
        "{%0,%1,%2,%3}, {%4,%5,%6,%7}, {%8,%9}, {%0,%1,%2,%3};\n"
        : "+f"(c[0]), "+f"(c[1]), "+f"(c[2]), "+f"(c[3])
        : "r"(a[0]), "r"(a[1]), "r"(a[2]), "r"(a[3]), "r"(b0), "r"(b1));
}

// ---------------- tensor-core GEMM (3xBF16, pre-split inputs) ----------------
// C[M=NPAD, N] = A[M,K] @ W[K,N]. A = (aSel? Q : P) bf16 hi/lo [M,K].
// W given as pre-transposed bf16 hi/lo [N,K] at g_Wh/g_Wl + woff.
// OUTB: write bf16 hi/lo to (bSel? Q : P); else fp32 to (f32Sel==1? g_A : g_B).
template <bool RELU, bool SCALED, bool OUTB>
__global__ __launch_bounds__(512) void tgemm_kernel(
    int K, int N, int aSel, int f32Sel, int bSel, long woff,
    const float* __restrict__ bias)
{
    constexpr int BM = 128, BN = 128, BK = 32, BKP = 40;
    __shared__ __align__(16) __nv_bfloat16 As_hi[BM][BKP];
    __shared__ __align__(16) __nv_bfloat16 As_lo[BM][BKP];
    __shared__ __align__(16) __nv_bfloat16 Bs_hi[BN][BKP];
    __shared__ __align__(16) __nv_bfloat16 Bs_lo[BN][BKP];

    const __nv_bfloat16* Ah = aSel ? g_Qh : g_Ph;
    const __nv_bfloat16* Al = aSel ? g_Ql : g_Pl;
    const __nv_bfloat16* Wh = g_Wh + woff;
    const __nv_bfloat16* Wl = g_Wl + woff;

    const int bm = blockIdx.y * BM;
    const int bn = blockIdx.x * BN;
    const int tid  = threadIdx.x;
    const int warp = tid >> 5;
    const int lane = tid & 31;
    const int warp_m = warp >> 2;
    const int warp_n = warp & 3;

    float acc[2][4][4];
#pragma unroll
    for (int i = 0; i < 2; i++)
#pragma unroll
        for (int j = 0; j < 4; j++)
#pragma unroll
            for (int r = 0; r < 4; r++) acc[i][j][r] = 0.f;

    // tile-fill mapping: 512 threads, 4 per row (8 bf16 = 16B each)
    const int frow = tid >> 2;          // 0..127
    const int fseg = (tid & 3) << 3;    // 0,8,16,24

    // ldmatrix per-lane addressing (validated in R6)
    const int a_row = lane & 15;
    const int a_koff = (lane >> 4) << 3;
    const int b_row = (lane & 7) + ((lane & 16) >> 1);
    const int b_koff = lane & 8;

    const __nv_bfloat16* pAh = Ah + (long)(bm + frow) * K + fseg;
    const __nv_bfloat16* pAl = Al + (long)(bm + frow) * K + fseg;
    const __nv_bfloat16* pBh = Wh + (long)(bn + frow) * K + fseg;
    const __nv_bfloat16* pBl = Wl + (long)(bn + frow) * K + fseg;

    uint4 rah = *(const uint4*)pAh;
    uint4 ral = *(const uint4*)pAl;
    uint4 rbh = *(const uint4*)pBh;
    uint4 rbl = *(const uint4*)pBl;

    for (int k0 = 0; k0 < K; k0 += BK) {
        *(uint4*)&As_hi[frow][fseg] = rah;
        *(uint4*)&As_lo[frow][fseg] = ral;
        *(uint4*)&Bs_hi[frow][fseg] = rbh;
        *(uint4*)&Bs_lo[frow][fseg] = rbl;
        __syncthreads();

        if (k0 + BK < K) {
            rah = *(const uint4*)(pAh + k0 + BK);
            ral = *(const uint4*)(pAl + k0 + BK);
            rbh = *(const uint4*)(pBh + k0 + BK);
            rbl = *(const uint4*)(pBl + k0 + BK);
        }

#pragma unroll
        for (int ks = 0; ks < BK; ks += 16) {
            uint32_t ah[2][4], al[2][4];
#pragma unroll
            for (int mt = 0; mt < 2; mt++) {
                int m0 = warp_m * 32 + mt * 16;
                ldsm4(ah[mt][0], ah[mt][1], ah[mt][2], ah[mt][3],
                      &As_hi[m0 + a_row][ks + a_koff]);
                ldsm4(al[mt][0], al[mt][1], al[mt][2], al[mt][3],
                      &As_lo[m0 + a_row][ks + a_koff]);
            }
#pragma unroll
            for (int pair = 0; pair < 2; pair++) {
                int n0 = warp_n * 32 + pair * 16;
                uint32_t bh0, bh1, bh2, bh3, bl0, bl1, bl2, bl3;
                ldsm4(bh0, bh1, bh2, bh3, &Bs_hi[n0 + b_row][ks + b_koff]);
                ldsm4(bl0, bl1, bl2, bl3, &Bs_lo[n0 + b_row][ks + b_koff]);
#pragma unroll
                for (int mt = 0; mt < 2; mt++) {
                    float* c0 = acc[mt][pair * 2 + 0];
                    float* c1 = acc[mt][pair * 2 + 1];
                    mma_bf16(c0, ah[mt], bh0, bh1);
                    mma_bf16(c0, ah[mt], bl0, bl1);
                    mma_bf16(c0, al[mt], bh0, bh1);
                    mma_bf16(c1, ah[mt], bh2, bh3);
                    mma_bf16(c1, ah[mt], bl2, bl3);
                    mma_bf16(c1, al[mt], bh2, bh3);
                }
            }
        }
        __syncthreads();
    }

    // epilogue
    float* Cf = (f32Sel == 1) ? g_A : g_B;
    __nv_bfloat16* Oh = bSel ? g_Qh : g_Ph;
    __nv_bfloat16* Ol = bSel ? g_Ql : g_Pl;

    const int rbase = bm + warp_m * 32 + (lane >> 2);
    const int cbase = bn + warp_n * 32 + 2 * (lane & 3);
#pragma unroll
    for (int mt = 0; mt < 2; mt++) {
#pragma unroll
        for (int half = 0; half < 2; half++) {
            int r = rbase + mt * 16 + half * 8;
            float scale = SCALED ? g_inv[r] : 1.0f;
            float bmsk  = SCALED ? g_msk[r] : 1.0f;
#pragma unroll
            for (int nt = 0; nt < 4; nt++) {
                int c = cbase + nt * 8;
                float2 bv = *(const float2*)(bias + c);
                float v0 = acc[mt][nt][half * 2 + 0] * scale + bv.x * bmsk;
                float v1 = acc[mt][nt][half * 2 + 1] * scale + bv.y * bmsk;
                if (RELU) { v0 = fmaxf(v0, 0.f); v1 = fmaxf(v1, 0.f); }
                if (OUTB) {
                    __nv_bfloat16 h0, h1, l0, l1;
                    split1(v0, h0, l0); split1(v1, h1, l1);
                    __nv_bfloat162 ph; ph.x = h0; ph.y = h1;
                    __nv_bfloat162 pl; pl.x = l0; pl.y = l1;
                    *(__nv_bfloat162*)(Oh + (long)r * N + c) = ph;
                    *(__nv_bfloat162*)(Ol + (long)r * N + c) = pl;
                } else {
                    *(float2*)(Cf + (long)r * N + c) = make_float2(v0, v1);
                }
            }
        }
    }
}

// ---------------- SIMT SGEMM for K=16 first layer (g_H -> g_A) ----------------
__global__ __launch_bounds__(256) void sgemm16_kernel(
    int N, const float* __restrict__ B, const float* __restrict__ bias)
{
    constexpr int BM = 128, BN = 128, BK = 16, TM = 8, TN = 8;
    __shared__ __align__(16) float As[BK][BM];
    __shared__ __align__(16) float Bs[BK][BN];
    const int bm = blockIdx.y * BM;
    const int bn = blockIdx.x * BN;
    const int tid = threadIdx.x;
    const int arow = tid >> 2, acol = (tid & 3) << 2;
    const int brow = tid >> 5, bcol = (tid & 31) << 2;
    const int ty = (tid >> 4) * TM, tx = (tid & 15) * TN;
    float acc[TM][TN];
#pragma unroll
    for (int i = 0; i < TM; i++)
#pragma unroll
        for (int j = 0; j < TN; j++) acc[i][j] = 0.f;
    const int K = 16;
#pragma unroll
    for (int i = 0; i < 2; i++) {
        int r = arow + i * 64;
        float4 v = *(const float4*)(g_H + (long)(bm + r) * K + acol);
        As[acol + 0][r] = v.x; As[acol + 1][r] = v.y;
        As[acol + 2][r] = v.z; As[acol + 3][r] = v.w;
    }
#pragma unroll
    for (int i = 0; i < 2; i++) {
        int r = brow + i * 8;
        *(float4*)(&Bs[r][bcol]) = *(const float4*)(B + (long)r * N + bn + bcol);
    }
    __syncthreads();
#pragma unroll
    for (int kk = 0; kk < BK; kk++) {
        float ra[TM], rb[TN];
        *(float4*)(ra)     = *(const float4*)(&As[kk][ty]);
        *(float4*)(ra + 4) = *(const float4*)(&As[kk][ty + 4]);
        *(float4*)(rb)     = *(const float4*)(&Bs[kk][tx]);
        *(float4*)(rb + 4) = *(const float4*)(&Bs[kk][tx + 4]);
#pragma unroll
        for (int i = 0; i < TM; i++)
#pragma unroll
            for (int j = 0; j < TN; j++) acc[i][j] += ra[i] * rb[j];
    }
#pragma unroll
    for (int i = 0; i < TM; i++) {
        long m = bm + ty + i;
        float* crow = g_A + m * N + bn + tx;
#pragma unroll
        for (int j = 0; j < TN; j += 4) {
            float4 bv = *(const float4*)(bias + bn + tx + j);
            float4 o;
            o.x = acc[i][j + 0] + bv.x; o.y = acc[i][j + 1] + bv.y;
            o.z = acc[i][j + 2] + bv.z; o.w = acc[i][j + 3] + bv.w;
            *(float4*)(crow + j) = o;
        }
    }
}

// ---------------- per-edge gather + relu + scatter-add ----------------
template <int H, int TPE, int ITERS>
__global__ __launch_bounds__(256) void edge_kernel(
    const int* __restrict__ ei,
    const float* __restrict__ w1p)
{
    static_assert(H == TPE * 4, "one float4 per thread");
    __shared__ __align__(16) float sw0[H];
    __shared__ __align__(16) float sw1[H];
    for (int i = threadIdx.x; i < H; i += 256) {
        sw0[i] = w1p[i];
        sw1[i] = w1p[H + i];
    }
    __syncthreads();

    constexpr int EPB = 256 / TPE;
    const int lane = threadIdx.x & (TPE - 1);
    const int sub  = threadIdx.x / TPE;
    const int v    = lane * 4;

    const float4 w0 = *(const float4*)(sw0 + v);
    const float4 w1 = *(const float4*)(sw1 + v);

    long base = (long)blockIdx.x * EPB * ITERS;
#pragma unroll 1
    for (int it = 0; it < ITERS; it++) {
        long e = base + (long)it * EPB + sub;
        if (e >= NE) return;
        int src = ei[e];
        int dst = ei[NE + e];
        float2 rp = g_rel[e];
        float4 a = *(const float4*)(g_A + (long)src * H + v);
        float4 z;
        z.x = fmaxf(fmaf(rp.x, w0.x, fmaf(rp.y, w1.x, a.x)), 0.f);
        z.y = fmaxf(fmaf(rp.x, w0.y, fmaf(rp.y, w1.y, a.y)), 0.f);
        z.z = fmaxf(fmaf(rp.x, w0.z, fmaf(rp.y, w1.z, a.z)), 0.f);
        z.w = fmaxf(fmaf(rp.x, w0.w, fmaf(rp.y, w1.w, a.w)), 0.f);
        float* out = g_B + (long)dst * H + v;
        atomicAdd(out + 0, z.x);
        atomicAdd(out + 1, z.y);
        atomicAdd(out + 2, z.z);
        atomicAdd(out + 3, z.w);
    }
}

// ---------------- head final: out[M,4] = g_B[M,512] @ W[512,4] + b ----------------
__global__ void k_head_final(const float* __restrict__ W,
                             const float* __restrict__ b, float* __restrict__ out) {
    int warp = (blockIdx.x * blockDim.x + threadIdx.x) >> 5;
    int lane = threadIdx.x & 31;
    if (warp >= NN) return;
    const float* x = g_B + (long)warp * 512;
    float a0 = 0.f, a1 = 0.f, a2 = 0.f, a3 = 0.f;
    for (int k = lane; k < 512; k += 32) {
        float xv = x[k];
        float4 w = *(const float4*)(W + k * 4);
        a0 = fmaf(xv, w.x, a0);
        a1 = fmaf(xv, w.y, a1);
        a2 = fmaf(xv, w.z, a2);
        a3 = fmaf(xv, w.w, a3);
    }
#pragma unroll
    for (int off = 16; off > 0; off >>= 1) {
        a0 += __shfl_down_sync(0xffffffffu, a0, off);
        a1 += __shfl_down_sync(0xffffffffu, a1, off);
        a2 += __shfl_down_sync(0xffffffffu, a2, off);
        a3 += __shfl_down_sync(0xffffffffu, a3, off);
    }
    if (lane == 0) {
        out[warp * 4 + 0] = a0 + b[0];
        out[warp * 4 + 1] = a1 + b[1];
        out[warp * 4 + 2] = a2 + b[2];
        out[warp * 4 + 3] = a3 + b[3];
    }
}

// ---------------- host orchestration ----------------
extern "C" void kernel_launch(void* const* d_in, const int* in_sizes, int n_in,
                              void* d_out, int out_size) {
    const float* h_in = (const float*)d_in[0];
    const float* pos  = (const float*)d_in[1];
    const int*   ei   = (const int*)d_in[2];   // int32 [2, NE]
    const float* l1_w1 = (const float*)d_in[3];
    const float* l1_b1 = (const float*)d_in[4];
    const float* l1_w2 = (const float*)d_in[5];
    const float* l1_b2 = (const float*)d_in[6];
    const float* l2_w1 = (const float*)d_in[7];
    const float* l2_b1 = (const float*)d_in[8];
    const float* l2_w2 = (const float*)d_in[9];
    const float* l2_b2 = (const float*)d_in[10];
    const float* l3_w1 = (const float*)d_in[11];
    const float* l3_b1 = (const float*)d_in[12];
    const float* l3_w2 = (const float*)d_in[13];
    const float* l3_b2 = (const float*)d_in[14];
    const float* l4_w1 = (const float*)d_in[15];
    const float* l4_b1 = (const float*)d_in[16];
    const float* l4_w2 = (const float*)d_in[17];
    const float* l4_b2 = (const float*)d_in[18];
    const float* hd_w1 = (const float*)d_in[19];
    const float* hd_b1 = (const float*)d_in[20];
    const float* hd_w2 = (const float*)d_in[21];
    const float* hd_b2 = (const float*)d_in[22];
    const float* hd_w3 = (const float*)d_in[23];
    const float* hd_b3 = (const float*)d_in[24];

    dim3 tb(32, 8);
    // one-time weight transpose+split (runs in-graph, cheap)
    k_tsplit<<<dim3(128/32, 128/32), tb>>>(l1_w2, 128, 128, OFF_L1W2);
    k_tsplit<<<dim3(256/32, 128/32), tb>>>(l2_w1, 128, 256, OFF_L2W1);
    k_tsplit<<<dim3(256/32, 256/32), tb>>>(l2_w2, 256, 256, OFF_L2W2);
    k_tsplit<<<dim3(1024/32, 256/32), tb>>>(l3_w1, 256, 1024, OFF_L3W1);
    k_tsplit<<<dim3(1024/32, 1024/32), tb>>>(l3_w2, 1024, 1024, OFF_L3W2);
    k_tsplit<<<dim3(1024/32, 1024/32), tb>>>(l4_w1, 1024, 1024, OFF_L4W1);
    k_tsplit<<<dim3(1024/32, 1024/32), tb>>>(l4_w2, 1024, 1024, OFF_L4W2);
    k_tsplit<<<dim3(1024/32, 1024/32), tb>>>(hd_w1, 1024, 1024, OFF_HDW1);
    k_tsplit<<<dim3(512/32, 1024/32), tb>>>(hd_w2, 1024, 512, OFF_HDW2);

    // prep
    k_zero_cnt<<<(NPAD + 255) / 256, 256>>>();
    k_prep<<<(NE + 255) / 256, 256>>>(ei, pos);
    k_fin<<<(NPAD + 255) / 256, 256>>>();
    k_copy_h<<<(NPAD * 16 / 4 + 255) / 256, 256>>>(h_in);

    dim3 g128(1, NPAD / 128), g256(2, NPAD / 128), g1024(8, NPAD / 128), g512(4, NPAD / 128);

    // --- layer 1: 16 -> 128 -> 128 ---
    sgemm16_kernel<<<g128, 256>>>(128, l1_w1, l1_b1);
    k_zero_B<<<2048, 256>>>((long)NPAD * 128 / 4);
    edge_kernel<128, 32, 4><<<(NE + 31) / 32, 256>>>(ei, l1_w1 + 16 * 128);
    k_splitB<<<2048, 256>>>((long)NPAD * 128 / 4);
    tgemm_kernel<true, true, true><<<g128, 512>>>(128, 128, 0, 0, 1, OFF_L1W2, l1_b2);

    // --- layer 2: 128 -> 256 -> 256 ---
    tgemm_kernel<false, false, false><<<g256, 512>>>(128, 256, 1, 1, 0, OFF_L2W1, l2_b1);
    k_zero_B<<<2048, 256>>>((long)NPAD * 256 / 4);
    edge_kernel<256, 64, 4><<<(NE + 15) / 16, 256>>>(ei, l2_w1 + 128 * 256);
    k_splitB<<<2048, 256>>>((long)NPAD * 256 / 4);
    tgemm_kernel<true, true, true><<<g256, 512>>>(256, 256, 0, 0, 1, OFF_L2W2, l2_b2);

    // --- layer 3: 256 -> 1024 -> 1024 ---
    tgemm_kernel<false, false, false><<<g1024, 512>>>(256, 1024, 1, 1, 0, OFF_L3W1, l3_b1);
    k_zero_B<<<4096, 256>>>((long)NPAD * 1024 / 4);
    edge_kernel<1024, 256, 16><<<(NE + 15) / 16, 256>>>(ei, l3_w1 + 256 * 1024);
    k_splitB<<<4096, 256>>>((long)NPAD * 1024 / 4);
    tgemm_kernel<true, true, true><<<g1024, 512>>>(1024, 1024, 0, 0, 1, OFF_L3W2, l3_b2);

    // --- layer 4: 1024 -> 1024 -> 1024 ---
    tgemm_kernel<false, false, false><<<g1024, 512>>>(1024, 1024, 1, 1, 0, OFF_L4W1, l4_b1);
    k_zero_B<<<4096, 256>>>((long)NPAD * 1024 / 4);
    edge_kernel<1024, 256, 16><<<(NE + 15) / 16, 256>>>(ei, l4_w1 + 1024 * 1024);
    k_splitB<<<4096, 256>>>((long)NPAD * 1024 / 4);
    tgemm_kernel<true, true, true><<<g1024, 512>>>(1024, 1024, 0, 0, 1, OFF_L4W2, l4_b2);

    // --- head: 1024 -> 1024 -> 512 -> 4 ---
    tgemm_kernel<true, false, true><<<g1024, 512>>>(1024, 1024, 1, 0, 0, OFF_HDW1, hd_b1);
    tgemm_kernel<true, false, false><<<g512, 512>>>(1024, 512, 0, 2, 0, OFF_HDW2, hd_b2);
    k_head_final<<<(NN * 32 + 255) / 256, 256>>>(hd_w3, hd_b3, (float*)d_out);
}

// round 8
// speedup vs baseline: 2.9830x; 1.6372x over previous
#include <cuda_runtime.h>
#include <cuda_bf16.h>
#include <cstdint>

#define NN    20000
#define NPAD  20096   // 157 * 128
#define NE    320000

// ---------------- scratch (static device memory, no allocs) ----------------
__device__ float  g_H[(size_t)NPAD * 16];     // input features (padded)
__device__ float  g_A[(size_t)NPAD * 1024];   // GEMM1 output (fp32, read by agg kernel)
__device__ float  g_B[(size_t)NPAD * 1024];   // hd2 out (fp32)
__device__ __nv_bfloat16 g_Ph[(size_t)NPAD * 1024];  // agg output (hi)
__device__ __nv_bfloat16 g_Pl[(size_t)NPAD * 1024];  // agg output (lo)
__device__ __nv_bfloat16 g_Qh[(size_t)NPAD * 1024];  // GEMM2 epilogue out (hi)
__device__ __nv_bfloat16 g_Ql[(size_t)NPAD * 1024];  // GEMM2 epilogue out (lo)
__device__ __nv_bfloat16 g_Wh[5095424];       // transposed weights (hi)
__device__ __nv_bfloat16 g_Wl[5095424];       // transposed weights (lo)
// CSR by destination
__device__ int    g_icnt[NPAD];
__device__ int    g_off[NPAD + 1];
__device__ int    g_cur[NPAD];
__device__ int    g_srcs[NE];
__device__ float2 g_crel[NE];
__device__ float  g_inv[NPAD];
__device__ float  g_msk[NPAD];

// weight offsets in g_Wh/g_Wl (element index)
#define OFF_L1W2 0L
#define OFF_L2W1 16384L
#define OFF_L2W2 49152L
#define OFF_L3W1 114688L
#define OFF_L3W2 376832L
#define OFF_L4W1 1425408L
#define OFF_L4W2 2473984L
#define OFF_HDW1 3522560L
#define OFF_HDW2 4571136L

__device__ __forceinline__ void split1(float a, __nv_bfloat16& h, __nv_bfloat16& l) {
    h = __float2bfloat16(a);
    l = __float2bfloat16(a - __bfloat162float(h));
}

// ---------------- prep kernels ----------------
__global__ void k_zero_icnt() {
    int i = blockIdx.x * blockDim.x + threadIdx.x;
    if (i < NPAD) g_icnt[i] = 0;
}

__global__ void k_count(const int* __restrict__ ei) {
    int e = blockIdx.x * blockDim.x + threadIdx.x;
    if (e < NE) atomicAdd(&g_icnt[ei[NE + e]], 1);
}

// single-block exclusive scan over g_icnt -> g_off/g_cur
__global__ __launch_bounds__(1024) void k_scan() {
    __shared__ int sh[1024];
    __shared__ int carry;
    int tid = threadIdx.x;
    if (tid == 0) carry = 0;
    __syncthreads();
    for (int base = 0; base < NPAD; base += 1024) {
        int i = base + tid;
        int v = (i < NPAD) ? g_icnt[i] : 0;
        sh[tid] = v;
        __syncthreads();
#pragma unroll
        for (int off = 1; off < 1024; off <<= 1) {
            int t = (tid >= off) ? sh[tid - off] : 0;
            __syncthreads();
            if (tid >= off) sh[tid] += t;
            __syncthreads();
        }
        int incl = sh[tid];
        int c = carry;
        if (i < NPAD) {
            g_off[i] = c + incl - v;
            g_cur[i] = c + incl - v;
        }
        __syncthreads();
        if (tid == 1023) carry = c + incl;
        __syncthreads();
    }
    if (tid == 0) g_off[NPAD] = carry;
}

__global__ void k_scatter(const int* __restrict__ ei, const float* __restrict__ pos) {
    int e = blockIdx.x * blockDim.x + threadIdx.x;
    if (e < NE) {
        int s = ei[e];
        int d = ei[NE + e];
        int p = atomicAdd(&g_cur[d], 1);
        g_srcs[p] = s;
        float2 ps = ((const float2*)pos)[s];
        float2 pd = ((const float2*)pos)[d];
        g_crel[p] = make_float2(ps.x - pd.x, ps.y - pd.y);
    }
}

__global__ void k_fin() {
    int i = blockIdx.x * blockDim.x + threadIdx.x;
    if (i < NPAD) {
        float c = (float)g_icnt[i];
        g_inv[i] = 1.0f / fmaxf(c, 1.0f);
        g_msk[i] = (c > 0.0f) ? 1.0f : 0.0f;
    }
}

__global__ void k_copy_h(const float* __restrict__ src) {
    int i = blockIdx.x * blockDim.x + threadIdx.x;
    if (i < NPAD * 16 / 4) {
        float4 v = (i < NN * 16 / 4) ? ((const float4*)src)[i] : make_float4(0.f, 0.f, 0.f, 0.f);
        ((float4*)g_H)[i] = v;
    }
}

// transpose + split: W[K,N] (row-major, ld=N) -> g_Wh/g_Wl[off + n*K + k]
__global__ void k_tsplit(const float* __restrict__ W, int K, int N, long off) {
    __shared__ float tile[32][33];
    int bx = blockIdx.x, by = blockIdx.y;
    int tx = threadIdx.x, ty = threadIdx.y;  // block (32,8)
#pragma unroll
    for (int j = 0; j < 4; j++) {
        int k = by * 32 + ty + j * 8;
        int n = bx * 32 + tx;
        tile[ty + j * 8][tx] = W[(long)k * N + n];
    }
    __syncthreads();
#pragma unroll
    for (int j = 0; j < 4; j++) {
        int n = bx * 32 + ty + j * 8;
        int k = by * 32 + tx;
        float v = tile[tx][ty + j * 8];
        __nv_bfloat16 h, l;
        split1(v, h, l);
        g_Wh[off + (long)n * K + k] = h;
        g_Wl[off + (long)n * K + k] = l;
    }
}

// ---------------- mma helpers ----------------
__device__ __forceinline__ void ldsm4(uint32_t& r0, uint32_t& r1, uint32_t& r2, uint32_t& r3,
                                      const void* p) {
    uint32_t addr = (uint32_t)__cvta_generic_to_shared(p);
    asm volatile("ldmatrix.sync.aligned.m8n8.x4.shared.b16 {%0,%1,%2,%3}, [%4];\n"
                 : "=r"(r0), "=r"(r1), "=r"(r2), "=r"(r3) : "r"(addr));
}

__device__ __forceinline__ void mma_bf16(float* c, const uint32_t* a, uint32_t b0, uint32_t b1) {
    asm volatile(
        "mma.sync.aligned.m16n8k16.row.col.f32.bf16.bf16.f32 "
        "{%0,%1,%2,%3}, {%4,%5,%6,%7}, {%8,%9}, {%0,%1,%2,%3};\n"
        : "+f"(c[0]), "+f"(c[1]), "+f"(c[2]), "+f"(c[3])
        : "r"(a[0]), "r"(a[1]), "r"(a[2]), "r"(a[3]), "r"(b0), "r"(b1));
}

// ---------------- tensor-core GEMM (3xBF16, pre-split inputs) ----------------
// C[M=NPAD, N] = A[M,K] @ W[K,N]. A = (aSel? Q : P) bf16 hi/lo [M,K].
// W pre-transposed bf16 hi/lo [N,K] at g_Wh/g_Wl + woff.
// SCALED: gate bias by g_msk (row scale is pre-folded into agg).
// OUTB: write bf16 hi/lo to (bSel? Q : P); else fp32 to (f32Sel==1? g_A : g_B).
template <bool RELU, bool SCALED, bool OUTB>
__global__ __launch_bounds__(512) void tgemm_kernel(
    int K, int N, int aSel, int f32Sel, int bSel, long woff,
    const float* __restrict__ bias)
{
    constexpr int BM = 128, BN = 128, BK = 32, BKP = 40;
    __shared__ __align__(16) __nv_bfloat16 As_hi[BM][BKP];
    __shared__ __align__(16) __nv_bfloat16 As_lo[BM][BKP];
    __shared__ __align__(16) __nv_bfloat16 Bs_hi[BN][BKP];
    __shared__ __align__(16) __nv_bfloat16 Bs_lo[BN][BKP];

    const __nv_bfloat16* Ah = aSel ? g_Qh : g_Ph;
    const __nv_bfloat16* Al = aSel ? g_Ql : g_Pl;
    const __nv_bfloat16* Wh = g_Wh + woff;
    const __nv_bfloat16* Wl = g_Wl + woff;

    const int bm = blockIdx.y * BM;
    const int bn = blockIdx.x * BN;
    const int tid  = threadIdx.x;
    const int warp = tid >> 5;
    const int lane = tid & 31;
    const int warp_m = warp >> 2;
    const int warp_n = warp & 3;

    float acc[2][4][4];
#pragma unroll
    for (int i = 0; i < 2; i++)
#pragma unroll
        for (int j = 0; j < 4; j++)
#pragma unroll
            for (int r = 0; r < 4; r++) acc[i][j][r] = 0.f;

    const int frow = tid >> 2;
    const int fseg = (tid & 3) << 3;

    const int a_row = lane & 15;
    const int a_koff = (lane >> 4) << 3;
    const int b_row = (lane & 7) + ((lane & 16) >> 1);
    const int b_koff = lane & 8;

    const __nv_bfloat16* pAh = Ah + (long)(bm + frow) * K + fseg;
    const __nv_bfloat16* pAl = Al + (long)(bm + frow) * K + fseg;
    const __nv_bfloat16* pBh = Wh + (long)(bn + frow) * K + fseg;
    const __nv_bfloat16* pBl = Wl + (long)(bn + frow) * K + fseg;

    uint4 rah = *(const uint4*)pAh;
    uint4 ral = *(const uint4*)pAl;
    uint4 rbh = *(const uint4*)pBh;
    uint4 rbl = *(const uint4*)pBl;

    for (int k0 = 0; k0 < K; k0 += BK) {
        *(uint4*)&As_hi[frow][fseg] = rah;
        *(uint4*)&As_lo[frow][fseg] = ral;
        *(uint4*)&Bs_hi[frow][fseg] = rbh;
        *(uint4*)&Bs_lo[frow][fseg] = rbl;
        __syncthreads();

        if (k0 + BK < K) {
            rah = *(const uint4*)(pAh + k0 + BK);
            ral = *(const uint4*)(pAl + k0 + BK);
            rbh = *(const uint4*)(pBh + k0 + BK);
            rbl = *(const uint4*)(pBl + k0 + BK);
        }

#pragma unroll
        for (int ks = 0; ks < BK; ks += 16) {
            uint32_t ah[2][4], al[2][4];
#pragma unroll
            for (int mt = 0; mt < 2; mt++) {
                int m0 = warp_m * 32 + mt * 16;
                ldsm4(ah[mt][0], ah[mt][1], ah[mt][2], ah[mt][3],
                      &As_hi[m0 + a_row][ks + a_koff]);
                ldsm4(al[mt][0], al[mt][1], al[mt][2], al[mt][3],
                      &As_lo[m0 + a_row][ks + a_koff]);
            }
#pragma unroll
            for (int pair = 0; pair < 2; pair++) {
                int n0 = warp_n * 32 + pair * 16;
                uint32_t bh0, bh1, bh2, bh3, bl0, bl1, bl2, bl3;
                ldsm4(bh0, bh1, bh2, bh3, &Bs_hi[n0 + b_row][ks + b_koff]);
                ldsm4(bl0, bl1, bl2, bl3, &Bs_lo[n0 + b_row][ks + b_koff]);
#pragma unroll
                for (int mt = 0; mt < 2; mt++) {
                    float* c0 = acc[mt][pair * 2 + 0];
                    float* c1 = acc[mt][pair * 2 + 1];
                    mma_bf16(c0, ah[mt], bh0, bh1);
                    mma_bf16(c0, ah[mt], bl0, bl1);
                    mma_bf16(c0, al[mt], bh0, bh1);
                    mma_bf16(c1, ah[mt], bh2, bh3);
                    mma_bf16(c1, ah[mt], bl2, bl3);
                    mma_bf16(c1, al[mt], bh2, bh3);
                }
            }
        }
        __syncthreads();
    }

    // epilogue
    float* Cf = (f32Sel == 1) ? g_A : g_B;
    __nv_bfloat16* Oh = bSel ? g_Qh : g_Ph;
    __nv_bfloat16* Ol = bSel ? g_Ql : g_Pl;

    const int rbase = bm + warp_m * 32 + (lane >> 2);
    const int cbase = bn + warp_n * 32 + 2 * (lane & 3);
#pragma unroll
    for (int mt = 0; mt < 2; mt++) {
#pragma unroll
        for (int half = 0; half < 2; half++) {
            int r = rbase + mt * 16 + half * 8;
            float bmsk = SCALED ? g_msk[r] : 1.0f;
#pragma unroll
            for (int nt = 0; nt < 4; nt++) {
                int c = cbase + nt * 8;
                float2 bv = *(const float2*)(bias + c);
                float v0 = acc[mt][nt][half * 2 + 0] + bv.x * bmsk;
                float v1 = acc[mt][nt][half * 2 + 1] + bv.y * bmsk;
                if (RELU) { v0 = fmaxf(v0, 0.f); v1 = fmaxf(v1, 0.f); }
                if (OUTB) {
                    __nv_bfloat16 h0, h1, l0, l1;
                    split1(v0, h0, l0); split1(v1, h1, l1);
                    __nv_bfloat162 ph; ph.x = h0; ph.y = h1;
                    __nv_bfloat162 pl; pl.x = l0; pl.y = l1;
                    *(__nv_bfloat162*)(Oh + (long)r * N + c) = ph;
                    *(__nv_bfloat162*)(Ol + (long)r * N + c) = pl;
                } else {
                    *(float2*)(Cf + (long)r * N + c) = make_float2(v0, v1);
                }
            }
        }
    }
}

// ---------------- SIMT SGEMM for K=16 first layer (g_H -> g_A) ----------------
__global__ __launch_bounds__(256) void sgemm16_kernel(
    int N, const float* __restrict__ B, const float* __restrict__ bias)
{
    constexpr int BM = 128, BN = 128, BK = 16, TM = 8, TN = 8;
    __shared__ __align__(16) float As[BK][BM];
    __shared__ __align__(16) float Bs[BK][BN];
    const int bm = blockIdx.y * BM;
    const int bn = blockIdx.x * BN;
    const int tid = threadIdx.x;
    const int arow = tid >> 2, acol = (tid & 3) << 2;
    const int brow = tid >> 5, bcol = (tid & 31) << 2;
    const int ty = (tid >> 4) * TM, tx = (tid & 15) * TN;
    float acc[TM][TN];
#pragma unroll
    for (int i = 0; i < TM; i++)
#pragma unroll
        for (int j = 0; j < TN; j++) acc[i][j] = 0.f;
    const int K = 16;
#pragma unroll
    for (int i = 0; i < 2; i++) {
        int r = arow + i * 64;
        float4 v = *(const float4*)(g_H + (long)(bm + r) * K + acol);
        As[acol + 0][r] = v.x; As[acol + 1][r] = v.y;
        As[acol + 2][r] = v.z; As[acol + 3][r] = v.w;
    }
#pragma unroll
    for (int i = 0; i < 2; i++) {
        int r = brow + i * 8;
        *(float4*)(&Bs[r][bcol]) = *(const float4*)(B + (long)r * N + bn + bcol);
    }
    __syncthreads();
#pragma unroll
    for (int kk = 0; kk < BK; kk++) {
        float ra[TM], rb[TN];
        *(float4*)(ra)     = *(const float4*)(&As[kk][ty]);
        *(float4*)(ra + 4) = *(const float4*)(&As[kk][ty + 4]);
        *(float4*)(rb)     = *(const float4*)(&Bs[kk][tx]);
        *(float4*)(rb + 4) = *(const float4*)(&Bs[kk][tx + 4]);
#pragma unroll
        for (int i = 0; i < TM; i++)
#pragma unroll
            for (int j = 0; j < TN; j++) acc[i][j] += ra[i] * rb[j];
    }
#pragma unroll
    for (int i = 0; i < TM; i++) {
        long m = bm + ty + i;
        float* crow = g_A + m * N + bn + tx;
#pragma unroll
        for (int j = 0; j < TN; j += 4) {
            float4 bv = *(const float4*)(bias + bn + tx + j);
            float4 o;
            o.x = acc[i][j + 0] + bv.x; o.y = acc[i][j + 1] + bv.y;
            o.z = acc[i][j + 2] + bv.z; o.w = acc[i][j + 3] + bv.w;
            *(float4*)(crow + j) = o;
        }
    }
}

// ---------------- CSR aggregation: for each dst row, sum relu(A[src]+rel.w1p) ----------------
// Folds inv_cnt scaling and bf16 hi/lo split into the write. RPB rows per 256-thread block.
template <int H, int RPB>
__global__ __launch_bounds__(256) void k_agg(const float* __restrict__ w1p) {
    constexpr int TPR = H / 4;
    static_assert(TPR * RPB == 256, "block mapping");
    __shared__ __align__(16) float sw0[H];
    __shared__ __align__(16) float sw1[H];
    for (int i = threadIdx.x; i < H; i += 256) {
        sw0[i] = w1p[i];
        sw1[i] = w1p[H + i];
    }
    __syncthreads();

    const int lr   = threadIdx.x / TPR;
    const int lane = threadIdx.x % TPR;
    const int row  = blockIdx.x * RPB + lr;
    const int v    = lane * 4;

    const float4 w0 = *(const float4*)(sw0 + v);
    const float4 w1 = *(const float4*)(sw1 + v);

    const int beg = g_off[row];
    const int end = g_off[row + 1];

    float4 acc = make_float4(0.f, 0.f, 0.f, 0.f);
    for (int j = beg; j < end; j++) {
        int src = __ldg(g_srcs + j);
        float2 rp = __ldg(g_crel + j);
        float4 a = *(const float4*)(g_A + (long)src * H + v);
        acc.x += fmaxf(fmaf(rp.x, w0.x, fmaf(rp.y, w1.x, a.x)), 0.f);
        acc.y += fmaxf(fmaf(rp.x, w0.y, fmaf(rp.y, w1.y, a.y)), 0.f);
        acc.z += fmaxf(fmaf(rp.x, w0.z, fmaf(rp.y, w1.z, a.z)), 0.f);
        acc.w += fmaxf(fmaf(rp.x, w0.w, fmaf(rp.y, w1.w, a.w)), 0.f);
    }
    float s = g_inv[row];
    acc.x *= s; acc.y *= s; acc.z *= s; acc.w *= s;

    __nv_bfloat16 h0, h1, h2, h3, l0, l1, l2, l3;
    split1(acc.x, h0, l0); split1(acc.y, h1, l1);
    split1(acc.z, h2, l2); split1(acc.w, h3, l3);
    __nv_bfloat162 ph0; ph0.x = h0; ph0.y = h1;
    __nv_bfloat162 ph1; ph1.x = h2; ph1.y = h3;
    __nv_bfloat162 pl0; pl0.x = l0; pl0.y = l1;
    __nv_bfloat162 pl1; pl1.x = l2; pl1.y = l3;
    long o = (long)row * H + v;
    *(__nv_bfloat162*)(g_Ph + o)     = ph0;
    *(__nv_bfloat162*)(g_Ph + o + 2) = ph1;
    *(__nv_bfloat162*)(g_Pl + o)     = pl0;
    *(__nv_bfloat162*)(g_Pl + o + 2) = pl1;
}

// ---------------- head final: out[M,4] = g_B[M,512] @ W[512,4] + b ----------------
__global__ void k_head_final(const float* __restrict__ W,
                             const float* __restrict__ b, float* __restrict__ out) {
    int warp = (blockIdx.x * blockDim.x + threadIdx.x) >> 5;
    int lane = threadIdx.x & 31;
    if (warp >= NN) return;
    const float* x = g_B + (long)warp * 512;
    float a0 = 0.f, a1 = 0.f, a2 = 0.f, a3 = 0.f;
    for (int k = lane; k < 512; k += 32) {
        float xv = x[k];
        float4 w = *(const float4*)(W + k * 4);
        a0 = fmaf(xv, w.x, a0);
        a1 = fmaf(xv, w.y, a1);
        a2 = fmaf(xv, w.z, a2);
        a3 = fmaf(xv, w.w, a3);
    }
#pragma unroll
    for (int off = 16; off > 0; off >>= 1) {
        a0 += __shfl_down_sync(0xffffffffu, a0, off);
        a1 += __shfl_down_sync(0xffffffffu, a1, off);
        a2 += __shfl_down_sync(0xffffffffu, a2, off);
        a3 += __shfl_down_sync(0xffffffffu, a3, off);
    }
    if (lane == 0) {
        out[warp * 4 + 0] = a0 + b[0];
        out[warp * 4 + 1] = a1 + b[1];
        out[warp * 4 + 2] = a2 + b[2];
        out[warp * 4 + 3] = a3 + b[3];
    }
}

// ---------------- host orchestration ----------------
extern "C" void kernel_launch(void* const* d_in, const int* in_sizes, int n_in,
                              void* d_out, int out_size) {
    const float* h_in = (const float*)d_in[0];
    const float* pos  = (const float*)d_in[1];
    const int*   ei   = (const int*)d_in[2];   // int32 [2, NE]
    const float* l1_w1 = (const float*)d_in[3];
    const float* l1_b1 = (const float*)d_in[4];
    const float* l1_w2 = (const float*)d_in[5];
    const float* l1_b2 = (const float*)d_in[6];
    const float* l2_w1 = (const float*)d_in[7];
    const float* l2_b1 = (const float*)d_in[8];
    const float* l2_w2 = (const float*)d_in[9];
    const float* l2_b2 = (const float*)d_in[10];
    const float* l3_w1 = (const float*)d_in[11];
    const float* l3_b1 = (const float*)d_in[12];
    const float* l3_w2 = (const float*)d_in[13];
    const float* l3_b2 = (const float*)d_in[14];
    const float* l4_w1 = (const float*)d_in[15];
    const float* l4_b1 = (const float*)d_in[16];
    const float* l4_w2 = (const float*)d_in[17];
    const float* l4_b2 = (const float*)d_in[18];
    const float* hd_w1 = (const float*)d_in[19];
    const float* hd_b1 = (const float*)d_in[20];
    const float* hd_w2 = (const float*)d_in[21];
    const float* hd_b2 = (const float*)d_in[22];
    const float* hd_w3 = (const float*)d_in[23];
    const float* hd_b3 = (const float*)d_in[24];

    dim3 tb(32, 8);
    // weight transpose+split
    k_tsplit<<<dim3(128/32, 128/32), tb>>>(l1_w2, 128, 128, OFF_L1W2);
    k_tsplit<<<dim3(256/32, 128/32), tb>>>(l2_w1, 128, 256, OFF_L2W1);
    k_tsplit<<<dim3(256/32, 256/32), tb>>>(l2_w2, 256, 256, OFF_L2W2);
    k_tsplit<<<dim3(1024/32, 256/32), tb>>>(l3_w1, 256, 1024, OFF_L3W1);
    k_tsplit<<<dim3(1024/32, 1024/32), tb>>>(l3_w2, 1024, 1024, OFF_L3W2);
    k_tsplit<<<dim3(1024/32, 1024/32), tb>>>(l4_w1, 1024, 1024, OFF_L4W1);
    k_tsplit<<<dim3(1024/32, 1024/32), tb>>>(l4_w2, 1024, 1024, OFF_L4W2);
    k_tsplit<<<dim3(1024/32, 1024/32), tb>>>(hd_w1, 1024, 1024, OFF_HDW1);
    k_tsplit<<<dim3(512/32, 1024/32), tb>>>(hd_w2, 1024, 512, OFF_HDW2);

    // CSR build + inv/mask + padded input copy
    k_zero_icnt<<<(NPAD + 255) / 256, 256>>>();
    k_count<<<(NE + 255) / 256, 256>>>(ei);
    k_scan<<<1, 1024>>>();
    k_scatter<<<(NE + 255) / 256, 256>>>(ei, pos);
    k_fin<<<(NPAD + 255) / 256, 256>>>();
    k_copy_h<<<(NPAD * 16 / 4 + 255) / 256, 256>>>(h_in);

    dim3 g128(1, NPAD / 128), g256(2, NPAD / 128), g1024(8, NPAD / 128), g512(4, NPAD / 128);

    // --- layer 1: 16 -> 128 -> 128 ---
    sgemm16_kernel<<<g128, 256>>>(128, l1_w1, l1_b1);
    k_agg<128, 8><<<NPAD / 8, 256>>>(l1_w1 + 16 * 128);
    tgemm_kernel<true, true, true><<<g128, 512>>>(128, 128, 0, 0, 1, OFF_L1W2, l1_b2);

    // --- layer 2: 128 -> 256 -> 256 ---
    tgemm_kernel<false, false, false><<<g256, 512>>>(128, 256, 1, 1, 0, OFF_L2W1, l2_b1);
    k_agg<256, 4><<<NPAD / 4, 256>>>(l2_w1 + 128 * 256);
    tgemm_kernel<true, true, true><<<g256, 512>>>(256, 256, 0, 0, 1, OFF_L2W2, l2_b2);

    // --- layer 3: 256 -> 1024 -> 1024 ---
    tgemm_kernel<false, false, false><<<g1024, 512>>>(256, 1024, 1, 1, 0, OFF_L3W1, l3_b1);
    k_agg<1024, 1><<<NPAD, 256>>>(l3_w1 + 256 * 1024);
    tgemm_kernel<true, true, true><<<g1024, 512>>>(1024, 1024, 0, 0, 1, OFF_L3W2, l3_b2);

    // --- layer 4: 1024 -> 1024 -> 1024 ---
    tgemm_kernel<false, false, false><<<g1024, 512>>>(1024, 1024, 1, 1, 0, OFF_L4W1, l4_b1);
    k_agg<1024, 1><<<NPAD, 256>>>(l4_w1 + 1024 * 1024);
    tgemm_kernel<true, true, true><<<g1024, 512>>>(1024, 1024, 0, 0, 1, OFF_L4W2, l4_b2);

    // --- head: 1024 -> 1024 -> 512 -> 4 ---
    tgemm_kernel<true, false, true><<<g1024, 512>>>(1024, 1024, 1, 0, 0, OFF_HDW1, hd_b1);
    tgemm_kernel<true, false, false><<<g512, 512>>>(1024, 512, 0, 2, 0, OFF_HDW2, hd_b2);
    k_head_final<<<(NN * 32 + 255) / 256, 256>>>(hd_w3, hd_b3, (float*)d_out);
}